// round 2
// baseline (speedup 1.0000x reference)
#include <cuda_runtime.h>
#include <cuda_fp16.h>

// Shapes (fixed)
#define B_      2048
#define OBS_    4096
#define G_      4096
#define I_      16
#define H_      8
#define A_      18
#define F_      36864   // OBS_ + G_*H_

#define BM      16      // batch rows per CTA
#define NP      8       // half2 pair rows (BM/2)
#define THREADS 256
#define GT      64      // gvfs per tile
#define FT      512     // obs-feature tile for phase 1

#define OBS_STRIDE 4100 // half2 per pair row (4096 + 4 pad)
#define WROW       130  // floats per gvf row in smem (128 + 2 pad)
#define HS         65   // h-major stride (in gs units) for gvf qW tile

// smem layout (bytes)
#define OBS_OFF   0
#define OBS_BYTES (NP * OBS_STRIDE * 4)            // 131200
#define WD_OFF    (OBS_OFF + OBS_BYTES)
#define WD_BYTES  (GT * WROW * 4)                  // 33280
#define QT_OFF    (WD_OFF + WD_BYTES)              // 164480
#define QT_BYTES  (8 * HS * A_ * 4)                // 37440 (>= 512*18*4 for phase 1)
#define IDX_OFF   (QT_OFF + QT_BYTES)              // 201920
#define IDX_BYTES (GT * 20 * 4)                    // 5120
#define STG_OFF   (IDX_OFF + IDX_BYTES)            // 207040
#define STG_BYTES (8 * 4 * 4 * 9 * 8)              // 9216
#define SMEM_BYTES (STG_OFF + STG_BYTES)           // 216256

using u64 = unsigned long long;

__device__ __forceinline__ u64 pack2(float lo, float hi) {
    u64 r;
    asm("mov.b64 %0, {%1, %2};" : "=l"(r) : "r"(__float_as_uint(lo)), "r"(__float_as_uint(hi)));
    return r;
}
__device__ __forceinline__ float2 unpack2(u64 v) {
    unsigned lo, hi;
    asm("mov.b64 {%0, %1}, %2;" : "=r"(lo), "=r"(hi) : "l"(v));
    float2 r; r.x = __uint_as_float(lo); r.y = __uint_as_float(hi);
    return r;
}
__device__ __forceinline__ u64 ffma2(u64 a, u64 b, u64 c) {
    u64 d;
    asm("fma.rn.f32x2 %0, %1, %2, %3;" : "=l"(d) : "l"(a), "l"(b), "l"(c));
    return d;
}
__device__ __forceinline__ u64 dup2(float w) { return pack2(w, w); }

__global__ __launch_bounds__(THREADS, 1)
void nibbler_fused_kernel(const float* __restrict__ obs,
                          const float* __restrict__ gvfW,
                          const float* __restrict__ qW,
                          const int*   __restrict__ gidx,
                          float* __restrict__ out) {
    extern __shared__ char smem[];
    __half2* sObs   = reinterpret_cast<__half2*>(smem + OBS_OFF);
    float*   sW     = reinterpret_cast<float*>(smem + WD_OFF);
    float*   sQ     = reinterpret_cast<float*>(smem + QT_OFF);
    int*     sIdx   = reinterpret_cast<int*>(smem + IDX_OFF);
    float2*  sStage = reinterpret_cast<float2*>(smem + STG_OFF);

    const int t     = threadIdx.x;
    const int bBase = blockIdx.x * BM;

    // ---- Phase 0: observation rows -> smem as fp16 half2 batch-pairs ----
    for (int e = t; e < NP * OBS_; e += THREADS) {
        int p = e >> 12;          // pair row 0..7
        int f = e & (OBS_ - 1);   // feature
        float v0 = obs[(size_t)(bBase + 2 * p) * OBS_ + f];
        float v1 = obs[(size_t)(bBase + 2 * p + 1) * OBS_ + f];
        sObs[p * OBS_STRIDE + f] = __floats2half2_rn(v0, v1);
    }

    const int sp = t & 3;   // owns batch locals 4sp..4sp+3
    const int gs = t >> 2;  // g-slot / feature slot 0..63

    const __half2* rowp0 = sObs + (2 * sp) * OBS_STRIDE;   // locals 4sp, 4sp+1
    const __half2* rowp1 = rowp0 + OBS_STRIDE;             // locals 4sp+2, 4sp+3

    // Accumulators: 4 batch rows x 9 action-pairs (f32x2 over actions 2a,2a+1)
    u64 acc[4][9];
#pragma unroll
    for (int b = 0; b < 4; b++)
#pragma unroll
        for (int ap = 0; ap < 9; ap++) acc[b][ap] = 0ULL;

    // ---- Phase 1: obs part of q ----
    for (int ft = 0; ft < OBS_; ft += FT) {
        __syncthreads();
        // qW[:, ft..ft+FT) transposed: sQ[fr*18 + a]  (coalesced gmem)
        for (int e = t; e < A_ * FT; e += THREADS) {
            int a  = e >> 9;          // FT = 512
            int fr = e & (FT - 1);
            sQ[fr * A_ + a] = qW[(size_t)a * F_ + ft + fr];
        }
        __syncthreads();
        for (int fr = gs; fr < FT; fr += 64) {
            const float* qr = sQ + fr * A_;
            u64 w2[9];
#pragma unroll
            for (int ap = 0; ap < 9; ap++)
                w2[ap] = *reinterpret_cast<const u64*>(qr + 2 * ap);
            float2 xa = __half22float2(rowp0[ft + fr]);
            float2 xb = __half22float2(rowp1[ft + fr]);
            float xs[4] = { xa.x, xa.y, xb.x, xb.y };
#pragma unroll
            for (int b = 0; b < 4; b++) {
                u64 xd = dup2(xs[b]);
#pragma unroll
                for (int ap = 0; ap < 9; ap++)
                    acc[b][ap] = ffma2(xd, w2[ap], acc[b][ap]);
            }
        }
    }

    // ---- Phase 2: GVF part, tiles of GT gvfs ----
    for (int g0 = 0; g0 < G_; g0 += GT) {
        __syncthreads();
        // idx tile (stride 20 for bank spread)
        for (int e = t; e < GT * I_; e += THREADS) {
            int gg = e >> 4, i = e & 15;
            sIdx[gg * 20 + i] = gidx[(size_t)(g0 + gg) * I_ + i];
        }
        // gvf_W tile, row stride 130
        for (int e = t; e < GT * 128; e += THREADS) {
            int gg = e >> 7, k = e & 127;
            sW[gg * WROW + k] = gvfW[(size_t)(g0 + gg) * 128 + k];
        }
        // qW gvf slice: (h,g)-major permuted layout sQ[(h*HS+gg)*18 + a]
        for (int e = t; e < A_ * (GT * H_); e += THREADS) {
            int a = e >> 9, col = e & 511;        // col = local feature = gg*8+h
            int h = col & 7, gg = col >> 3;
            sQ[(h * HS + gg) * A_ + a] = qW[(size_t)a * F_ + OBS_ + g0 * H_ + col];
        }
        __syncthreads();

        const int*   ip = sIdx + gs * 20;
        const float* wr = sW + gs * WROW;

        // gather 16 inputs for both batch pairs (half2 -> packed f32x2)
        u64 x0[I_], x1[I_];
#pragma unroll
        for (int i = 0; i < I_; i++) {
            int id = ip[i];
            float2 a2 = __half22float2(rowp0[id]);
            float2 b2 = __half22float2(rowp1[id]);
            x0[i] = pack2(a2.x, a2.y);
            x1[i] = pack2(b2.x, b2.y);
        }

#pragma unroll
        for (int h = 0; h < H_; h++) {
            const float* wh = wr + h * I_;
            u64 f0 = 0ULL, f1 = 0ULL;
#pragma unroll
            for (int i = 0; i < I_; i += 2) {
                float2 wp = *reinterpret_cast<const float2*>(wh + i);  // LDS.64
                u64 w0 = dup2(wp.x), w1 = dup2(wp.y);
                f0 = ffma2(x0[i],     w0, f0);
                f1 = ffma2(x1[i],     w0, f1);
                f0 = ffma2(x0[i + 1], w1, f0);
                f1 = ffma2(x1[i + 1], w1, f1);
            }
            float2 fa = unpack2(f0), fb = unpack2(f1);
            float fs[4] = { fmaxf(fa.x, 0.f), fmaxf(fa.y, 0.f),
                            fmaxf(fb.x, 0.f), fmaxf(fb.y, 0.f) };
            const float* qc = sQ + (h * HS + gs) * A_;
            u64 w2[9];
#pragma unroll
            for (int ap = 0; ap < 9; ap++)
                w2[ap] = *reinterpret_cast<const u64*>(qc + 2 * ap);
#pragma unroll
            for (int b = 0; b < 4; b++) {
                u64 fd = dup2(fs[b]);
#pragma unroll
                for (int ap = 0; ap < 9; ap++)
                    acc[b][ap] = ffma2(fd, w2[ap], acc[b][ap]);
            }
        }
    }

    // ---- Phase 3: reduce 8 g-slots per warp, then across the 8 warps ----
    const int lane = t & 31;
    const int wid  = t >> 5;
#pragma unroll
    for (int b = 0; b < 4; b++) {
#pragma unroll
        for (int ap = 0; ap < 9; ap++) {
            float2 v = unpack2(acc[b][ap]);
#pragma unroll
            for (int off = 4; off < 32; off <<= 1) {
                v.x += __shfl_xor_sync(0xffffffffu, v.x, off);
                v.y += __shfl_xor_sync(0xffffffffu, v.y, off);
            }
            if (lane < 4)
                sStage[(((wid * 4 + lane) * 4) + b) * 9 + ap] = v;
        }
    }
    __syncthreads();

    if (t < BM * 9) {
        int bl = t / 9, ap = t - bl * 9;     // bl = batch local 0..15
        int spp = bl >> 2, b = bl & 3;
        float sx = 0.f, sy = 0.f;
#pragma unroll
        for (int w = 0; w < 8; w++) {
            float2 v = sStage[(((w * 4 + spp) * 4) + b) * 9 + ap];
            sx += v.x; sy += v.y;
        }
        size_t o = (size_t)(bBase + bl) * A_ + 2 * ap;
        out[o]     = sx;
        out[o + 1] = sy;
    }
}

extern "C" void kernel_launch(void* const* d_in, const int* in_sizes, int n_in,
                              void* d_out, int out_size) {
    const float* obs  = (const float*)d_in[0];
    const float* gvfW = (const float*)d_in[1];
    const float* qW   = (const float*)d_in[2];
    const int*   gidx = (const int*)d_in[3];
    float* out = (float*)d_out;

    cudaFuncSetAttribute(nibbler_fused_kernel,
                         cudaFuncAttributeMaxDynamicSharedMemorySize, SMEM_BYTES);
    nibbler_fused_kernel<<<B_ / BM, THREADS, SMEM_BYTES>>>(obs, gvfW, qW, gidx, out);
}

// round 3
// speedup vs baseline: 1.4974x; 1.4974x over previous
#include <cuda_runtime.h>
#include <cuda_fp16.h>

// Shapes (fixed)
#define B_      2048
#define OBS_    4096
#define G_      4096
#define I_      16
#define H_      8
#define A_      18
#define F_      36864   // OBS_ + G_*H_

#define BM      16      // batch rows per CTA
#define NP      8       // half2 pair rows (BM/2)
#define THREADS 512
#define GT      64      // gvfs per tile
#define FT      512     // obs-feature tile for phase 1

#define OBS_STRIDE 4102 // half2 words per pair row (4096 + 6 pad) -> conflict-free sp stride
#define WROW       132  // floats per gvf row in smem (128 + 4 pad), 16B aligned rows
#define HS         65   // (h,g)-major stride for gvf qW tile

// smem layout (bytes)
#define OBS_OFF   0
#define OBS_BYTES (NP * OBS_STRIDE * 4)            // 131264
#define WD_OFF    (OBS_OFF + OBS_BYTES)            // 131264
#define WD_BYTES  (GT * WROW * 4)                  // 33792
#define QT_OFF    (WD_OFF + WD_BYTES)              // 165056
#define QT_BYTES  (H_ * HS * A_ * 4)               // 37440 (>= 512*18*4 for phase 1)
#define IDX_OFF   (QT_OFF + QT_BYTES)              // 202496
#define IDX_BYTES (GT * 20 * 4)                    // 5120
#define SMEM_BYTES (IDX_OFF + IDX_BYTES)           // 207616
// reduction stage aliases the gvf_W buffer (used only after last tile)
#define STG_OFF   WD_OFF                           // 16*8*2*9*8 = 18432 <= 33792

using u64 = unsigned long long;

__device__ __forceinline__ u64 pack2(float lo, float hi) {
    u64 r;
    asm("mov.b64 %0, {%1, %2};" : "=l"(r) : "r"(__float_as_uint(lo)), "r"(__float_as_uint(hi)));
    return r;
}
__device__ __forceinline__ float2 unpack2(u64 v) {
    unsigned lo, hi;
    asm("mov.b64 {%0, %1}, %2;" : "=r"(lo), "=r"(hi) : "l"(v));
    float2 r; r.x = __uint_as_float(lo); r.y = __uint_as_float(hi);
    return r;
}
__device__ __forceinline__ u64 ffma2(u64 a, u64 b, u64 c) {
    u64 d;
    asm("fma.rn.f32x2 %0, %1, %2, %3;" : "=l"(d) : "l"(a), "l"(b), "l"(c));
    return d;
}
__device__ __forceinline__ u64 dup2(float w) { return pack2(w, w); }

__global__ __launch_bounds__(THREADS, 1)
void nibbler_fused_kernel(const float* __restrict__ obs,
                          const float* __restrict__ gvfW,
                          const float* __restrict__ qW,
                          const int*   __restrict__ gidx,
                          float* __restrict__ out) {
    extern __shared__ char smem[];
    __half2* sObs   = reinterpret_cast<__half2*>(smem + OBS_OFF);
    float*   sW     = reinterpret_cast<float*>(smem + WD_OFF);
    float*   sQ     = reinterpret_cast<float*>(smem + QT_OFF);
    int*     sIdx   = reinterpret_cast<int*>(smem + IDX_OFF);
    float2*  sStage = reinterpret_cast<float2*>(smem + STG_OFF);

    const int t     = threadIdx.x;
    const int bBase = blockIdx.x * BM;

    // ---- Phase 0: observation -> smem as fp16 half2 batch-pairs (vectorized) ----
    // NP*OBS_/2 = 16384 uint2 groups (2 features each), 32 per thread
    for (int e = t; e < NP * (OBS_ / 2); e += THREADS) {
        int p  = e >> 11;            // pair row 0..7 (2048 groups/row)
        int f  = (e & 2047) * 2;     // feature
        float2 r0 = *reinterpret_cast<const float2*>(&obs[(size_t)(bBase + 2 * p) * OBS_ + f]);
        float2 r1 = *reinterpret_cast<const float2*>(&obs[(size_t)(bBase + 2 * p + 1) * OBS_ + f]);
        __half2 h0 = __floats2half2_rn(r0.x, r1.x);
        __half2 h1 = __floats2half2_rn(r0.y, r1.y);
        uint2 uv;
        uv.x = *reinterpret_cast<unsigned*>(&h0);
        uv.y = *reinterpret_cast<unsigned*>(&h1);
        *reinterpret_cast<uint2*>(&sObs[p * OBS_STRIDE + f]) = uv;
    }

    const int sp = t & 7;   // pair row (batch locals 2sp, 2sp+1)
    const int gs = t >> 3;  // g-slot / feature slot 0..63

    const __half2* rowp = sObs + sp * OBS_STRIDE;

    // Accumulators: 2 batch rows x 9 action-pairs (f32x2 over actions 2a,2a+1)
    u64 acc[2][9];
#pragma unroll
    for (int b = 0; b < 2; b++)
#pragma unroll
        for (int ap = 0; ap < 9; ap++) acc[b][ap] = 0ULL;

    // ---- Phase 1: obs part of q ----
    for (int ft = 0; ft < OBS_; ft += FT) {
        __syncthreads();
        // qW[:, ft..ft+FT) transposed: sQ[fr*18 + a]; float2 loads (A_*FT/2 = 4608 = 9/thread)
        for (int e = t; e < A_ * (FT / 2); e += THREADS) {
            int a  = e >> 8;              // FT/2 = 256
            int fr = (e & 255) * 2;
            float2 v = *reinterpret_cast<const float2*>(&qW[(size_t)a * F_ + ft + fr]);
            sQ[fr * A_ + a]       = v.x;
            sQ[(fr + 1) * A_ + a] = v.y;
        }
        __syncthreads();
#pragma unroll 4
        for (int k = 0; k < FT / 64; k++) {
            int fr = gs + k * 64;
            const float* qr = sQ + fr * A_;
            u64 w2[9];
#pragma unroll
            for (int ap = 0; ap < 9; ap++)
                w2[ap] = *reinterpret_cast<const u64*>(qr + 2 * ap);
            float2 xa = __half22float2(rowp[ft + fr]);
            u64 xd0 = dup2(xa.x), xd1 = dup2(xa.y);
#pragma unroll
            for (int ap = 0; ap < 9; ap++) {
                acc[0][ap] = ffma2(xd0, w2[ap], acc[0][ap]);
                acc[1][ap] = ffma2(xd1, w2[ap], acc[1][ap]);
            }
        }
    }

    // ---- Phase 2: GVF part, tiles of GT gvfs ----
    for (int g0 = 0; g0 < G_; g0 += GT) {
        __syncthreads();
        // idx tile: 256 int4 groups
        for (int e = t; e < GT * I_ / 4; e += THREADS) {
            int gg = e >> 2, j = (e & 3) * 4;
            int4 v = *reinterpret_cast<const int4*>(&gidx[(size_t)(g0 + gg) * I_ + j]);
            *reinterpret_cast<int4*>(&sIdx[gg * 20 + j]) = v;
        }
        // gvf_W tile: 2048 float4 groups (4/thread), row stride 132
        for (int e = t; e < GT * 128 / 4; e += THREADS) {
            int gg = e >> 5, k = (e & 31) * 4;
            float4 v = *reinterpret_cast<const float4*>(&gvfW[(size_t)(g0 + gg) * 128 + k]);
            *reinterpret_cast<float4*>(&sW[gg * WROW + k]) = v;
        }
        // qW gvf slice: (h,g)-major layout sQ[(h*HS+gg)*18 + a]; float4 src (2304 groups)
        for (int e = t; e < A_ * (GT * H_) / 4; e += THREADS) {
            int a = e >> 7, c4 = e & 127;     // 128 float4 per action row
            int col = c4 * 4;                  // local feature = gg*8 + h
            int gg = col >> 3, h = col & 7;    // h in {0,4}
            float4 v = *reinterpret_cast<const float4*>(
                &qW[(size_t)a * F_ + OBS_ + g0 * H_ + col]);
            sQ[((h + 0) * HS + gg) * A_ + a] = v.x;
            sQ[((h + 1) * HS + gg) * A_ + a] = v.y;
            sQ[((h + 2) * HS + gg) * A_ + a] = v.z;
            sQ[((h + 3) * HS + gg) * A_ + a] = v.w;
        }
        __syncthreads();

        const float* wr = sW + gs * WROW;

        // idx via LDS.128, gather batch-pair inputs as packed f32x2
        int idxv[I_];
#pragma unroll
        for (int j = 0; j < 4; j++)
            *reinterpret_cast<int4*>(&idxv[4 * j]) =
                *reinterpret_cast<const int4*>(&sIdx[gs * 20 + 4 * j]);
        u64 x[I_];
#pragma unroll
        for (int i = 0; i < I_; i++) {
            float2 a2 = __half22float2(rowp[idxv[i]]);
            x[i] = pack2(a2.x, a2.y);
        }

#pragma unroll
        for (int h = 0; h < H_; h++) {
            const float* wh = wr + h * I_;
            u64 f0 = 0ULL;
#pragma unroll
            for (int i = 0; i < I_; i += 2) {
                float2 wp = *reinterpret_cast<const float2*>(wh + i);   // LDS.64
                f0 = ffma2(x[i],     dup2(wp.x), f0);
                f0 = ffma2(x[i + 1], dup2(wp.y), f0);
            }
            float2 fa = unpack2(f0);
            float fs0 = fmaxf(fa.x, 0.f), fs1 = fmaxf(fa.y, 0.f);
            const float* qc = sQ + (h * HS + gs) * A_;
            u64 w2[9];
#pragma unroll
            for (int ap = 0; ap < 9; ap++)
                w2[ap] = *reinterpret_cast<const u64*>(qc + 2 * ap);
            u64 fd0 = dup2(fs0), fd1 = dup2(fs1);
#pragma unroll
            for (int ap = 0; ap < 9; ap++) {
                acc[0][ap] = ffma2(fd0, w2[ap], acc[0][ap]);
                acc[1][ap] = ffma2(fd1, w2[ap], acc[1][ap]);
            }
        }
    }

    // ---- Phase 3: reduce 4 gs per warp via shuffle, stage, final sum ----
    __syncthreads();   // sW last reads done; stage aliases it
    const int lane = t & 31;
    const int wid  = t >> 5;
#pragma unroll
    for (int b = 0; b < 2; b++) {
#pragma unroll
        for (int ap = 0; ap < 9; ap++) {
            float2 v = unpack2(acc[b][ap]);
            v.x += __shfl_xor_sync(0xffffffffu, v.x, 8);
            v.y += __shfl_xor_sync(0xffffffffu, v.y, 8);
            v.x += __shfl_xor_sync(0xffffffffu, v.x, 16);
            v.y += __shfl_xor_sync(0xffffffffu, v.y, 16);
            if (lane < 8)
                sStage[((wid * 8 + lane) * 2 + b) * 9 + ap] = v;
        }
    }
    __syncthreads();

    if (t < BM * 9) {
        int bl = t / 9, ap = t - bl * 9;   // bl = batch local 0..15
        int spp = bl >> 1, b = bl & 1;
        float sx = 0.f, sy = 0.f;
#pragma unroll
        for (int w = 0; w < 16; w++) {
            float2 v = sStage[((w * 8 + spp) * 2 + b) * 9 + ap];
            sx += v.x; sy += v.y;
        }
        size_t o = (size_t)(bBase + bl) * A_ + 2 * ap;
        out[o]     = sx;
        out[o + 1] = sy;
    }
}

extern "C" void kernel_launch(void* const* d_in, const int* in_sizes, int n_in,
                              void* d_out, int out_size) {
    const float* obs  = (const float*)d_in[0];
    const float* gvfW = (const float*)d_in[1];
    const float* qW   = (const float*)d_in[2];
    const int*   gidx = (const int*)d_in[3];
    float* out = (float*)d_out;

    cudaFuncSetAttribute(nibbler_fused_kernel,
                         cudaFuncAttributeMaxDynamicSharedMemorySize, SMEM_BYTES);
    nibbler_fused_kernel<<<B_ / BM, THREADS, SMEM_BYTES>>>(obs, gvfW, qW, gidx, out);
}

// round 4
// speedup vs baseline: 1.8923x; 1.2637x over previous
#include <cuda_runtime.h>
#include <cuda_fp16.h>

// Shapes (fixed)
#define B_      2048
#define OBS_    4096
#define G_      4096
#define I_      16
#define H_      8
#define A_      18
#define F_      36864   // OBS_ + G_*H_

#define BM      16      // batch rows per CTA
#define NP      8       // half2 pair rows (BM/2)
#define THREADS 512
#define GT      64      // gvfs per tile
#define FT      512     // obs-feature tile for phase 1
#define NT1     (OBS_ / FT)   // 8 phase-1 tiles
#define NT2     (G_ / GT)     // 64 phase-2 tiles

#define OBS_STRIDE 4102 // half2 words per pair row (4096 + 6 pad)
#define WROW       132  // floats per gvf row in smem (128 + 4 pad)
#define HS         65   // (h,g)-major stride for gvf qW tile

// smem layout (bytes)
#define OBS_OFF   0
#define OBS_BYTES (NP * OBS_STRIDE * 4)            // 131264
#define WD_OFF    (OBS_OFF + OBS_BYTES)            // 131264
#define WD_BYTES  (GT * WROW * 4)                  // 33792
#define QT_OFF    (WD_OFF + WD_BYTES)              // 165056
#define QT_BYTES  (H_ * HS * A_ * 4)               // 37440 (>= FT*18*4)
#define IDX_OFF   (QT_OFF + QT_BYTES)              // 202496
#define IDX_BYTES (GT * 20 * 4)                    // 5120
#define SMEM_BYTES (IDX_OFF + IDX_BYTES)           // 207616
#define STG_OFF   WD_OFF                           // reduction stage aliases gvf_W buf

using u64 = unsigned long long;

__device__ __forceinline__ u64 pack2(float lo, float hi) {
    u64 r;
    asm("mov.b64 %0, {%1, %2};" : "=l"(r) : "r"(__float_as_uint(lo)), "r"(__float_as_uint(hi)));
    return r;
}
__device__ __forceinline__ float2 unpack2(u64 v) {
    unsigned lo, hi;
    asm("mov.b64 {%0, %1}, %2;" : "=r"(lo), "=r"(hi) : "l"(v));
    float2 r; r.x = __uint_as_float(lo); r.y = __uint_as_float(hi);
    return r;
}
__device__ __forceinline__ u64 ffma2(u64 a, u64 b, u64 c) {
    u64 d;
    asm("fma.rn.f32x2 %0, %1, %2, %3;" : "=l"(d) : "l"(a), "l"(b), "l"(c));
    return d;
}
__device__ __forceinline__ u64 dup2(float w) { return pack2(w, w); }

__global__ __launch_bounds__(THREADS, 1)
void nibbler_fused_kernel(const float* __restrict__ obs,
                          const float* __restrict__ gvfW,
                          const float* __restrict__ qW,
                          const int*   __restrict__ gidx,
                          float* __restrict__ out) {
    extern __shared__ char smem[];
    __half2* sObs   = reinterpret_cast<__half2*>(smem + OBS_OFF);
    float*   sW     = reinterpret_cast<float*>(smem + WD_OFF);
    float*   sQ     = reinterpret_cast<float*>(smem + QT_OFF);
    int*     sIdx   = reinterpret_cast<int*>(smem + IDX_OFF);
    float2*  sStage = reinterpret_cast<float2*>(smem + STG_OFF);

    const int t     = threadIdx.x;
    const int bBase = blockIdx.x * BM;

    // ---- Phase 0: observation -> smem as fp16 half2 batch-pairs ----
    for (int e = t; e < NP * (OBS_ / 2); e += THREADS) {
        int p  = e >> 11;
        int f  = (e & 2047) * 2;
        float2 r0 = *reinterpret_cast<const float2*>(&obs[(size_t)(bBase + 2 * p) * OBS_ + f]);
        float2 r1 = *reinterpret_cast<const float2*>(&obs[(size_t)(bBase + 2 * p + 1) * OBS_ + f]);
        __half2 h0 = __floats2half2_rn(r0.x, r1.x);
        __half2 h1 = __floats2half2_rn(r0.y, r1.y);
        uint2 uv;
        uv.x = *reinterpret_cast<unsigned*>(&h0);
        uv.y = *reinterpret_cast<unsigned*>(&h1);
        *reinterpret_cast<uint2*>(&sObs[p * OBS_STRIDE + f]) = uv;
    }

    const int sp = t & 7;   // pair row (batch locals 2sp, 2sp+1)
    const int gs = t >> 3;  // g-slot / feature slot 0..63
    const __half2* rowp = sObs + sp * OBS_STRIDE;

    // Accumulators: 2 batch rows x 9 action-pairs (f32x2 over actions 2a,2a+1)
    u64 acc[2][9];
#pragma unroll
    for (int b = 0; b < 2; b++)
#pragma unroll
        for (int ap = 0; ap < 9; ap++) acc[b][ap] = 0ULL;

    // ===================== Phase 1: obs part of q =====================
    // Prefetch regs: 9 float2 per thread (A_*FT/2 = 4608 = 9*512)
    float2 pre1[9];
#pragma unroll
    for (int j = 0; j < 9; j++) {
        int e = j * THREADS + t;
        int a = e >> 8, fr = (e & 255) * 2;
        pre1[j] = *reinterpret_cast<const float2*>(&qW[(size_t)a * F_ + 0 + fr]);
    }

    // Phase-2 prefetch regs (loaded during last phase-1 tile)
    float4 preW[4];           // gvfW: 2048 float4 = 4*512
    float4 preQ4[4];          // qW slice: first 2048 of 2304 float4
    float4 preQx;             // qW slice: last 256 float4 (t<256)
    int4   preI;              // idx: 256 int4 (t<256)

    for (int ti = 0; ti < NT1; ti++) {
        const int ft = ti * FT;
        __syncthreads();
        // store prefetched qW tile: sQ[fr*18 + a]
#pragma unroll
        for (int j = 0; j < 9; j++) {
            int e = j * THREADS + t;
            int a = e >> 8, fr = (e & 255) * 2;
            sQ[fr * A_ + a]       = pre1[j].x;
            sQ[(fr + 1) * A_ + a] = pre1[j].y;
        }
        __syncthreads();

        // prefetch next tile (or phase-2 tile 0 on the last iteration)
        if (ti + 1 < NT1) {
            const int ftn = ft + FT;
#pragma unroll
            for (int j = 0; j < 9; j++) {
                int e = j * THREADS + t;
                int a = e >> 8, fr = (e & 255) * 2;
                pre1[j] = *reinterpret_cast<const float2*>(&qW[(size_t)a * F_ + ftn + fr]);
            }
        } else {
            // phase-2 tile 0 prefetch
            if (t < 256) {
                preI = *reinterpret_cast<const int4*>(&gidx[(size_t)(t >> 2) * I_ + (t & 3) * 4]);
                int e2 = 2048 + t;
                int a = e2 >> 7, c4 = e2 & 127;
                preQx = *reinterpret_cast<const float4*>(&qW[(size_t)a * F_ + OBS_ + c4 * 4]);
            }
#pragma unroll
            for (int j = 0; j < 4; j++) {
                int e = j * THREADS + t;
                int gg = e >> 5, k = (e & 31) * 4;
                preW[j] = *reinterpret_cast<const float4*>(&gvfW[(size_t)gg * 128 + k]);
            }
#pragma unroll
            for (int j = 0; j < 4; j++) {
                int e = j * THREADS + t;
                int a = e >> 7, c4 = e & 127;
                preQ4[j] = *reinterpret_cast<const float4*>(&qW[(size_t)a * F_ + OBS_ + c4 * 4]);
            }
        }

        // compute this tile
#pragma unroll 4
        for (int k = 0; k < FT / 64; k++) {
            int fr = gs + k * 64;
            const float* qr = sQ + fr * A_;
            u64 w2[9];
#pragma unroll
            for (int ap = 0; ap < 9; ap++)
                w2[ap] = *reinterpret_cast<const u64*>(qr + 2 * ap);
            float2 xa = __half22float2(rowp[ft + fr]);
            u64 xd0 = dup2(xa.x), xd1 = dup2(xa.y);
#pragma unroll
            for (int ap = 0; ap < 9; ap++) {
                acc[0][ap] = ffma2(xd0, w2[ap], acc[0][ap]);
                acc[1][ap] = ffma2(xd1, w2[ap], acc[1][ap]);
            }
        }
    }

    // ===================== Phase 2: GVF part =====================
    for (int ti = 0; ti < NT2; ti++) {
        __syncthreads();
        // store prefetched tile
        if (t < 256) {
            *reinterpret_cast<int4*>(&sIdx[(t >> 2) * 20 + (t & 3) * 4]) = preI;
            int e2 = 2048 + t;
            int c4 = e2 & 127, a = e2 >> 7;
            int col = c4 * 4, gg = col >> 3, h = col & 7;
            sQ[((h + 0) * HS + gg) * A_ + a] = preQx.x;
            sQ[((h + 1) * HS + gg) * A_ + a] = preQx.y;
            sQ[((h + 2) * HS + gg) * A_ + a] = preQx.z;
            sQ[((h + 3) * HS + gg) * A_ + a] = preQx.w;
        }
#pragma unroll
        for (int j = 0; j < 4; j++) {
            int e = j * THREADS + t;
            int gg = e >> 5, k = (e & 31) * 4;
            *reinterpret_cast<float4*>(&sW[gg * WROW + k]) = preW[j];
        }
#pragma unroll
        for (int j = 0; j < 4; j++) {
            int e = j * THREADS + t;
            int a = e >> 7, c4 = e & 127;
            int col = c4 * 4, gg = col >> 3, h = col & 7;
            sQ[((h + 0) * HS + gg) * A_ + a] = preQ4[j].x;
            sQ[((h + 1) * HS + gg) * A_ + a] = preQ4[j].y;
            sQ[((h + 2) * HS + gg) * A_ + a] = preQ4[j].z;
            sQ[((h + 3) * HS + gg) * A_ + a] = preQ4[j].w;
        }
        __syncthreads();

        // prefetch next tile
        if (ti + 1 < NT2) {
            const int g0n = (ti + 1) * GT;
            if (t < 256) {
                preI = *reinterpret_cast<const int4*>(
                    &gidx[(size_t)(g0n + (t >> 2)) * I_ + (t & 3) * 4]);
                int e2 = 2048 + t;
                int a = e2 >> 7, c4 = e2 & 127;
                preQx = *reinterpret_cast<const float4*>(
                    &qW[(size_t)a * F_ + OBS_ + g0n * H_ + c4 * 4]);
            }
#pragma unroll
            for (int j = 0; j < 4; j++) {
                int e = j * THREADS + t;
                int gg = e >> 5, k = (e & 31) * 4;
                preW[j] = *reinterpret_cast<const float4*>(
                    &gvfW[(size_t)(g0n + gg) * 128 + k]);
            }
#pragma unroll
            for (int j = 0; j < 4; j++) {
                int e = j * THREADS + t;
                int a = e >> 7, c4 = e & 127;
                preQ4[j] = *reinterpret_cast<const float4*>(
                    &qW[(size_t)a * F_ + OBS_ + g0n * H_ + c4 * 4]);
            }
        }

        // compute this tile: i-outer, h-inner (low register pressure)
        const float* wr = sW + gs * WROW;
        const int*   ip = sIdx + gs * 20;
        u64 f[H_];
#pragma unroll
        for (int h = 0; h < H_; h++) f[h] = 0ULL;

#pragma unroll
        for (int ipr = 0; ipr < I_ / 2; ipr++) {
            int2 id2 = *reinterpret_cast<const int2*>(ip + 2 * ipr);   // LDS.64
            float2 a0 = __half22float2(rowp[id2.x]);
            float2 a1 = __half22float2(rowp[id2.y]);
            u64 x0 = pack2(a0.x, a0.y);
            u64 x1 = pack2(a1.x, a1.y);
#pragma unroll
            for (int h = 0; h < H_; h++) {
                float2 wp = *reinterpret_cast<const float2*>(wr + h * I_ + 2 * ipr); // LDS.64
                f[h] = ffma2(x0, dup2(wp.x), f[h]);
                f[h] = ffma2(x1, dup2(wp.y), f[h]);
            }
        }

#pragma unroll
        for (int h = 0; h < H_; h++) {
            float2 fa = unpack2(f[h]);
            u64 fd0 = dup2(fmaxf(fa.x, 0.f));
            u64 fd1 = dup2(fmaxf(fa.y, 0.f));
            const float* qc = sQ + (h * HS + gs) * A_;
            u64 w2[9];
#pragma unroll
            for (int ap = 0; ap < 9; ap++)
                w2[ap] = *reinterpret_cast<const u64*>(qc + 2 * ap);
#pragma unroll
            for (int ap = 0; ap < 9; ap++) {
                acc[0][ap] = ffma2(fd0, w2[ap], acc[0][ap]);
                acc[1][ap] = ffma2(fd1, w2[ap], acc[1][ap]);
            }
        }
    }

    // ---- Phase 3: reduce 4 gs per warp via shuffle, stage, final sum ----
    __syncthreads();   // sW reads done; stage aliases it
    const int lane = t & 31;
    const int wid  = t >> 5;
#pragma unroll
    for (int b = 0; b < 2; b++) {
#pragma unroll
        for (int ap = 0; ap < 9; ap++) {
            float2 v = unpack2(acc[b][ap]);
            v.x += __shfl_xor_sync(0xffffffffu, v.x, 8);
            v.y += __shfl_xor_sync(0xffffffffu, v.y, 8);
            v.x += __shfl_xor_sync(0xffffffffu, v.x, 16);
            v.y += __shfl_xor_sync(0xffffffffu, v.y, 16);
            if (lane < 8)
                sStage[((wid * 8 + lane) * 2 + b) * 9 + ap] = v;
        }
    }
    __syncthreads();

    if (t < BM * 9) {
        int bl = t / 9, ap = t - bl * 9;
        int spp = bl >> 1, b = bl & 1;
        float sx = 0.f, sy = 0.f;
#pragma unroll
        for (int w = 0; w < 16; w++) {
            float2 v = sStage[((w * 8 + spp) * 2 + b) * 9 + ap];
            sx += v.x; sy += v.y;
        }
        size_t o = (size_t)(bBase + bl) * A_ + 2 * ap;
        out[o]     = sx;
        out[o + 1] = sy;
    }
}

extern "C" void kernel_launch(void* const* d_in, const int* in_sizes, int n_in,
                              void* d_out, int out_size) {
    const float* obs  = (const float*)d_in[0];
    const float* gvfW = (const float*)d_in[1];
    const float* qW   = (const float*)d_in[2];
    const int*   gidx = (const int*)d_in[3];
    float* out = (float*)d_out;

    cudaFuncSetAttribute(nibbler_fused_kernel,
                         cudaFuncAttributeMaxDynamicSharedMemorySize, SMEM_BYTES);
    nibbler_fused_kernel<<<B_ / BM, THREADS, SMEM_BYTES>>>(obs, gvfW, qW, gidx, out);
}

// round 5
// speedup vs baseline: 2.0675x; 1.0926x over previous
#include <cuda_runtime.h>
#include <cuda_fp16.h>

// Shapes (fixed)
#define B_      2048
#define OBS_    4096
#define G_      4096
#define I_      16
#define H_      8
#define A_      18
#define F_      36864   // OBS_ + G_*H_

#define BM      16      // batch rows per CTA
#define THREADS 256
#define GT      64      // gvfs per tile
#define FT      512     // obs-feature tile for phase 1
#define NT1     8       // phase-1 tiles
#define NT2     64      // phase-2 tiles

#define QSTRIDE 4100    // uint2 words per quad row (4096 + 4 pad)
#define ROWS2   520     // phase-2 qW tile rows = 8*65 (h*65+gg)
#define HS      65

// smem layout (bytes)
#define OBS_OFF   0
#define OBS_BYTES (4 * QSTRIDE * 8)          // 131200 (4 quad rows of uint2)
#define SQ_OFF    (OBS_OFF + OBS_BYTES)
#define SQ_BYTES  (ROWS2 * 20 * 4)           // 41600 (>= 512*20*4 for phase 1)
#define WD_OFF    (SQ_OFF + SQ_BYTES)
#define WD_BYTES  (GT * 528)                 // 33792 (64 rows x 528B fp16-dup weights)
#define IDX_OFF   (WD_OFF + WD_BYTES)
#define IDX_BYTES (GT * 20 * 4)              // 5120
#define SMEM_BYTES (IDX_OFF + IDX_BYTES)     // 211712
#define STG_OFF   WD_OFF                     // reduction stage aliases weight buf

using u64 = unsigned long long;

// ---- scratch (prep-kernel outputs) ----
__device__ float    qT1g[NT1 * 512 * 20];       // phase-1 qW tiles, transposed+padded
__device__ float    qT2g[NT2 * ROWS2 * 20];     // phase-2 qW tiles, (h,g)-major
__device__ unsigned gvfWdg[G_ * 128];           // gvfW as duplicated half2

__device__ __forceinline__ u64 pack2(float lo, float hi) {
    u64 r;
    asm("mov.b64 %0, {%1, %2};" : "=l"(r) : "r"(__float_as_uint(lo)), "r"(__float_as_uint(hi)));
    return r;
}
__device__ __forceinline__ float2 unpack2(u64 v) {
    unsigned lo, hi;
    asm("mov.b64 {%0, %1}, %2;" : "=r"(lo), "=r"(hi) : "l"(v));
    float2 r; r.x = __uint_as_float(lo); r.y = __uint_as_float(hi);
    return r;
}
__device__ __forceinline__ u64 ffma2(u64 a, u64 b, u64 c) {
    u64 d;
    asm("fma.rn.f32x2 %0, %1, %2, %3;" : "=l"(d) : "l"(a), "l"(b), "l"(c));
    return d;
}
__device__ __forceinline__ u64 dup2(float w) { return pack2(w, w); }
__device__ __forceinline__ __half2 as_h2(unsigned u) {
    return *reinterpret_cast<__half2*>(&u);
}

// ================= prep kernels =================
__global__ void prep_qT1(const float* __restrict__ qW) {
    int e = blockIdx.x * 256 + threadIdx.x;
    if (e >= NT1 * 512 * 20) return;
    int tile = e / (512 * 20);
    int rem  = e - tile * (512 * 20);
    int fr = rem / 20, a = rem - fr * 20;
    float v = 0.f;
    if (a < A_) v = qW[(size_t)a * F_ + tile * FT + fr];
    qT1g[e] = v;
}

__global__ void prep_qT2(const float* __restrict__ qW) {
    int e = blockIdx.x * 256 + threadIdx.x;
    if (e >= NT2 * ROWS2 * 20) return;
    int tile = e / (ROWS2 * 20);
    int rem  = e - tile * (ROWS2 * 20);
    int r = rem / 20, a = rem - r * 20;
    int h = r / HS, gg = r - h * HS;
    float v = 0.f;
    if (a < A_ && gg < GT && h < H_)
        v = qW[(size_t)a * F_ + OBS_ + tile * (GT * H_) + gg * H_ + h];
    qT2g[e] = v;
}

__global__ void prep_gvfWd(const float* __restrict__ gvfW) {
    int e = blockIdx.x * 256 + threadIdx.x;
    if (e >= G_ * 128) return;
    __half h = __float2half(gvfW[e]);
    unsigned hu = (unsigned)__half_as_ushort(h);
    gvfWdg[e] = hu | (hu << 16);
}

// ================= main kernel =================
__global__ __launch_bounds__(THREADS, 1)
void nibbler_fused_kernel(const float* __restrict__ obs,
                          const int*   __restrict__ gidx,
                          float* __restrict__ out) {
    extern __shared__ char smem[];
    uint2*  sObs   = reinterpret_cast<uint2*>(smem + OBS_OFF);   // [4 quads][QSTRIDE]
    float*  sQ     = reinterpret_cast<float*>(smem + SQ_OFF);
    char*   sWd    = smem + WD_OFF;
    int*    sIdx   = reinterpret_cast<int*>(smem + IDX_OFF);
    float2* sStage = reinterpret_cast<float2*>(smem + STG_OFF);

    const int t     = threadIdx.x;
    const int bBase = blockIdx.x * BM;

    // ---- Phase 0: obs -> smem as 4-row quads (uint2 of two half2) ----
    for (int e = t; e < 4 * (OBS_ / 4); e += THREADS) {
        int q = e >> 10;            // quad row 0..3 (rows 4q..4q+3)
        int f = (e & 1023) * 4;     // feature base
        const float* r0 = &obs[(size_t)(bBase + 4 * q + 0) * OBS_ + f];
        const float* r1 = &obs[(size_t)(bBase + 4 * q + 1) * OBS_ + f];
        const float* r2 = &obs[(size_t)(bBase + 4 * q + 2) * OBS_ + f];
        const float* r3 = &obs[(size_t)(bBase + 4 * q + 3) * OBS_ + f];
        float4 v0 = *reinterpret_cast<const float4*>(r0);
        float4 v1 = *reinterpret_cast<const float4*>(r1);
        float4 v2 = *reinterpret_cast<const float4*>(r2);
        float4 v3 = *reinterpret_cast<const float4*>(r3);
        uint2* dst = &sObs[q * QSTRIDE + f];
        __half2 a0 = __floats2half2_rn(v0.x, v1.x), b0 = __floats2half2_rn(v2.x, v3.x);
        __half2 a1 = __floats2half2_rn(v0.y, v1.y), b1 = __floats2half2_rn(v2.y, v3.y);
        __half2 a2 = __floats2half2_rn(v0.z, v1.z), b2 = __floats2half2_rn(v2.z, v3.z);
        __half2 a3 = __floats2half2_rn(v0.w, v1.w), b3 = __floats2half2_rn(v2.w, v3.w);
        uint4 s0, s1;
        s0.x = *reinterpret_cast<unsigned*>(&a0); s0.y = *reinterpret_cast<unsigned*>(&b0);
        s0.z = *reinterpret_cast<unsigned*>(&a1); s0.w = *reinterpret_cast<unsigned*>(&b1);
        s1.x = *reinterpret_cast<unsigned*>(&a2); s1.y = *reinterpret_cast<unsigned*>(&b2);
        s1.z = *reinterpret_cast<unsigned*>(&a3); s1.w = *reinterpret_cast<unsigned*>(&b3);
        *reinterpret_cast<uint4*>(dst)     = s0;
        *reinterpret_cast<uint4*>(dst + 2) = s1;
    }

    const int sp = t & 3;     // quad row: batch rows 4sp..4sp+3
    const int gs = t >> 2;    // g-slot / feature slot 0..63
    const uint2* qrow = sObs + sp * QSTRIDE;

    // Accumulators: 4 batch rows x 9 action-pairs (f32x2 over actions)
    u64 acc[4][9];
#pragma unroll
    for (int r = 0; r < 4; r++)
#pragma unroll
        for (int ap = 0; ap < 9; ap++) acc[r][ap] = 0ULL;

    // ======= Phase 1: obs part of q =======
    float4 pre1[10];   // 2560 float4 per tile = 10 * 256
#pragma unroll
    for (int j = 0; j < 10; j++)
        pre1[j] = *reinterpret_cast<const float4*>(&qT1g[(j * THREADS + t) * 4]);

    float4 preQ[11];   // 2600 float4 (last partial)
    uint4  preW[8];    // 2048 uint4
    int4   preI;       // 256 int4

    for (int ti = 0; ti < NT1; ti++) {
        const int ft = ti * FT;
        __syncthreads();
#pragma unroll
        for (int j = 0; j < 10; j++)
            *reinterpret_cast<float4*>(&sQ[(j * THREADS + t) * 4]) = pre1[j];
        __syncthreads();

        if (ti + 1 < NT1) {
            const float* src = &qT1g[(ti + 1) * (512 * 20)];
#pragma unroll
            for (int j = 0; j < 10; j++)
                pre1[j] = *reinterpret_cast<const float4*>(&src[(j * THREADS + t) * 4]);
        } else {
            // prefetch phase-2 tile 0
#pragma unroll
            for (int j = 0; j < 11; j++) {
                int e = j * THREADS + t;
                if (e < 2600)
                    preQ[j] = *reinterpret_cast<const float4*>(&qT2g[e * 4]);
            }
#pragma unroll
            for (int j = 0; j < 8; j++)
                preW[j] = *reinterpret_cast<const uint4*>(&gvfWdg[(j * THREADS + t) * 4]);
            preI = *reinterpret_cast<const int4*>(&gidx[(size_t)t * 4]);
        }

#pragma unroll 4
        for (int k = 0; k < FT / 64; k++) {
            int fr = gs + k * 64;
            const float* qr = sQ + fr * 20;
            const ulonglong2* q2 = reinterpret_cast<const ulonglong2*>(qr);
            u64 w2[9];
            ulonglong2 qa = q2[0], qb = q2[1], qc = q2[2], qd = q2[3];
            w2[0] = qa.x; w2[1] = qa.y; w2[2] = qb.x; w2[3] = qb.y;
            w2[4] = qc.x; w2[5] = qc.y; w2[6] = qd.x; w2[7] = qd.y;
            w2[8] = *reinterpret_cast<const u64*>(qr + 16);
            uint2 xv = qrow[ft + fr];
            float2 c01 = __half22float2(as_h2(xv.x));
            float2 c23 = __half22float2(as_h2(xv.y));
            u64 fd[4] = { dup2(c01.x), dup2(c01.y), dup2(c23.x), dup2(c23.y) };
#pragma unroll
            for (int r = 0; r < 4; r++)
#pragma unroll
                for (int ap = 0; ap < 9; ap++)
                    acc[r][ap] = ffma2(fd[r], w2[ap], acc[r][ap]);
        }
    }

    // ======= Phase 2: GVF part =======
    const __half2 hz = __floats2half2_rn(0.f, 0.f);
    for (int ti = 0; ti < NT2; ti++) {
        __syncthreads();
        // store prefetched tile (flat copies, conflict-free)
#pragma unroll
        for (int j = 0; j < 11; j++) {
            int e = j * THREADS + t;
            if (e < 2600)
                *reinterpret_cast<float4*>(&sQ[e * 4]) = preQ[j];
        }
#pragma unroll
        for (int j = 0; j < 8; j++) {
            int e = j * THREADS + t;
            int gg = e >> 5, kk = e & 31;
            *reinterpret_cast<uint4*>(sWd + gg * 528 + kk * 16) = preW[j];
        }
        {
            int gg = t >> 2, jj = t & 3;
            *reinterpret_cast<int4*>(&sIdx[gg * 20 + jj * 4]) = preI;
        }
        __syncthreads();

        if (ti + 1 < NT2) {
            const float* srcQ = &qT2g[(size_t)(ti + 1) * (ROWS2 * 20)];
#pragma unroll
            for (int j = 0; j < 11; j++) {
                int e = j * THREADS + t;
                if (e < 2600)
                    preQ[j] = *reinterpret_cast<const float4*>(&srcQ[e * 4]);
            }
            const unsigned* srcW = &gvfWdg[(size_t)(ti + 1) * (GT * 128)];
#pragma unroll
            for (int j = 0; j < 8; j++)
                preW[j] = *reinterpret_cast<const uint4*>(&srcW[(j * THREADS + t) * 4]);
            preI = *reinterpret_cast<const int4*>(
                &gidx[(size_t)((ti + 1) * GT) * I_ + t * 4]);
        }

        // --- compute: 1 gvf, 4 batch rows per thread ---
        int idxv[I_];
#pragma unroll
        for (int j = 0; j < 4; j++)
            *reinterpret_cast<int4*>(&idxv[4 * j]) =
                *reinterpret_cast<const int4*>(&sIdx[gs * 20 + 4 * j]);

        uint2 xv[I_];
#pragma unroll
        for (int i = 0; i < I_; i++) xv[i] = qrow[idxv[i]];   // LDS.64 gathers

        const uint4* wrow = reinterpret_cast<const uint4*>(sWd + gs * 528);
#pragma unroll
        for (int h = 0; h < H_; h++) {
            __half2 f01 = hz, f23 = hz;
#pragma unroll
            for (int j = 0; j < 4; j++) {
                uint4 wv = wrow[h * 4 + j];    // 4 dup'd fp16 weights
                f01 = __hfma2(as_h2(xv[4*j+0].x), as_h2(wv.x), f01);
                f23 = __hfma2(as_h2(xv[4*j+0].y), as_h2(wv.x), f23);
                f01 = __hfma2(as_h2(xv[4*j+1].x), as_h2(wv.y), f01);
                f23 = __hfma2(as_h2(xv[4*j+1].y), as_h2(wv.y), f23);
                f01 = __hfma2(as_h2(xv[4*j+2].x), as_h2(wv.z), f01);
                f23 = __hfma2(as_h2(xv[4*j+2].y), as_h2(wv.z), f23);
                f01 = __hfma2(as_h2(xv[4*j+3].x), as_h2(wv.w), f01);
                f23 = __hfma2(as_h2(xv[4*j+3].y), as_h2(wv.w), f23);
            }
            f01 = __hmax2(f01, hz);
            f23 = __hmax2(f23, hz);
            float2 c01 = __half22float2(f01);
            float2 c23 = __half22float2(f23);
            u64 fd[4] = { dup2(c01.x), dup2(c01.y), dup2(c23.x), dup2(c23.y) };

            const float* qr = sQ + (h * HS + gs) * 20;
            const ulonglong2* q2 = reinterpret_cast<const ulonglong2*>(qr);
            u64 w2[9];
            ulonglong2 qa = q2[0], qb = q2[1], qc = q2[2], qd = q2[3];
            w2[0] = qa.x; w2[1] = qa.y; w2[2] = qb.x; w2[3] = qb.y;
            w2[4] = qc.x; w2[5] = qc.y; w2[6] = qd.x; w2[7] = qd.y;
            w2[8] = *reinterpret_cast<const u64*>(qr + 16);
#pragma unroll
            for (int r = 0; r < 4; r++)
#pragma unroll
                for (int ap = 0; ap < 9; ap++)
                    acc[r][ap] = ffma2(fd[r], w2[ap], acc[r][ap]);
        }
    }

    // ======= Phase 3: reduce over the 64 g-slots =======
    __syncthreads();   // weight buffer reads done; stage aliases it
    const int lane = t & 31;
    const int wid  = t >> 5;
#pragma unroll
    for (int r = 0; r < 4; r++) {
#pragma unroll
        for (int ap = 0; ap < 9; ap++) {
            float2 v = unpack2(acc[r][ap]);
            v.x += __shfl_xor_sync(0xffffffffu, v.x, 4);
            v.y += __shfl_xor_sync(0xffffffffu, v.y, 4);
            v.x += __shfl_xor_sync(0xffffffffu, v.x, 8);
            v.y += __shfl_xor_sync(0xffffffffu, v.y, 8);
            v.x += __shfl_xor_sync(0xffffffffu, v.x, 16);
            v.y += __shfl_xor_sync(0xffffffffu, v.y, 16);
            if (lane < 4)
                sStage[((wid * 4 + lane) * 4 + r) * 9 + ap] = v;
        }
    }
    __syncthreads();

    if (t < BM * 9) {
        int bl = t / 9, ap = t - bl * 9;   // bl = 4*sp + r
        int spp = bl >> 2, r = bl & 3;
        float sx = 0.f, sy = 0.f;
#pragma unroll
        for (int w = 0; w < 8; w++) {
            float2 v = sStage[((w * 4 + spp) * 4 + r) * 9 + ap];
            sx += v.x; sy += v.y;
        }
        size_t o = (size_t)(bBase + bl) * A_ + 2 * ap;
        out[o]     = sx;
        out[o + 1] = sy;
    }
}

extern "C" void kernel_launch(void* const* d_in, const int* in_sizes, int n_in,
                              void* d_out, int out_size) {
    const float* obs  = (const float*)d_in[0];
    const float* gvfW = (const float*)d_in[1];
    const float* qW   = (const float*)d_in[2];
    const int*   gidx = (const int*)d_in[3];
    float* out = (float*)d_out;

    prep_qT1<<<(NT1 * 512 * 20 + 255) / 256, 256>>>(qW);
    prep_qT2<<<(NT2 * ROWS2 * 20 + 255) / 256, 256>>>(qW);
    prep_gvfWd<<<(G_ * 128 + 255) / 256, 256>>>(gvfW);

    cudaFuncSetAttribute(nibbler_fused_kernel,
                         cudaFuncAttributeMaxDynamicSharedMemorySize, SMEM_BYTES);
    nibbler_fused_kernel<<<B_ / BM, THREADS, SMEM_BYTES>>>(obs, gidx, out);
}

// round 6
// speedup vs baseline: 2.5676x; 1.2419x over previous
#include <cuda_runtime.h>
#include <cuda_fp16.h>
#include <cstdint>

// Shapes (fixed)
#define B_      2048
#define OBS_    4096
#define G_      4096
#define I_      16
#define H_      8
#define A_      18
#define F_      36864

#define BM      16
#define THREADS 512
#define GT      64
#define FT      256
#define NT1     16
#define NT2     64

#define QSTRIDE 4100    // uint2 words per quad row (4096 + 4 pad)
#define HS      65

// smem layout (bytes)
#define OBS_OFF   0
#define OBS_BYTES (4 * QSTRIDE * 8)          // 131200
#define SQ_OFF    (OBS_OFF + OBS_BYTES)
#define SQ_BYTES  41600                       // phase2: 520*20*4; phase1: 2*256*20*4=40960
#define WD_OFF    (SQ_OFF + SQ_BYTES)         // 172800
#define WD_BYTES  (GT * 544)                  // 34816 (rows skewed to 544B)
#define IDX_OFF   (WD_OFF + WD_BYTES)         // 207616
#define IDX_BYTES (GT * 80)                   // 5120
#define SMEM_BYTES (IDX_OFF + IDX_BYTES)      // 212736
#define STG_OFF   WD_OFF                      // reduction stage aliases weights

using u64 = unsigned long long;

// ---- scratch (prep outputs) ----
__device__ float qT1g[NT1 * FT * 20];        // phase-1 qW tiles, transposed+padded
__device__ float qT2g[NT2 * 520 * 20];       // phase-2 qW tiles, (h,g)-major
__device__ uint2 gvfWl[G_ * 64];             // weights: [g][hh][p][hp] dup'd half2 pairs

__device__ __forceinline__ u64 pack2(float lo, float hi) {
    u64 r;
    asm("mov.b64 %0, {%1, %2};" : "=l"(r) : "r"(__float_as_uint(lo)), "r"(__float_as_uint(hi)));
    return r;
}
__device__ __forceinline__ float2 unpack2(u64 v) {
    unsigned lo, hi;
    asm("mov.b64 {%0, %1}, %2;" : "=r"(lo), "=r"(hi) : "l"(v));
    float2 r; r.x = __uint_as_float(lo); r.y = __uint_as_float(hi);
    return r;
}
__device__ __forceinline__ u64 ffma2(u64 a, u64 b, u64 c) {
    u64 d;
    asm("fma.rn.f32x2 %0, %1, %2, %3;" : "=l"(d) : "l"(a), "l"(b), "l"(c));
    return d;
}
__device__ __forceinline__ u64 dup2(float w) { return pack2(w, w); }
__device__ __forceinline__ __half2 as_h2(unsigned u) { return *reinterpret_cast<__half2*>(&u); }

#define CPA16(dst, src) asm volatile("cp.async.cg.shared.global [%0], [%1], 16;" :: "r"(dst), "l"(src))
#define CPCOMMIT()      asm volatile("cp.async.commit_group;")
#define CPWAIT0()       asm volatile("cp.async.wait_group 0;")
#define CPWAIT1()       asm volatile("cp.async.wait_group 1;")

// ================= prep kernels =================
__global__ void prep_qT1(const float* __restrict__ qW) {
    int e = blockIdx.x * 256 + threadIdx.x;
    if (e >= NT1 * FT * 20) return;
    int tile = e / (FT * 20);
    int rem  = e - tile * (FT * 20);
    int fr = rem / 20, a = rem - fr * 20;
    float v = 0.f;
    if (a < A_) v = qW[(size_t)a * F_ + tile * FT + fr];
    qT1g[e] = v;
}

__global__ void prep_qT2(const float* __restrict__ qW) {
    int e = blockIdx.x * 256 + threadIdx.x;
    if (e >= NT2 * 520 * 20) return;
    int tile = e / (520 * 20);
    int rem  = e - tile * (520 * 20);
    int r = rem / 20, a = rem - r * 20;
    int h = r / HS, gg = r - h * HS;
    float v = 0.f;
    if (a < A_ && gg < GT && h < H_)
        v = qW[(size_t)a * F_ + OBS_ + tile * (GT * H_) + gg * H_ + h];
    qT2g[e] = v;
}

__global__ void prep_gvfWl(const float* __restrict__ gvfW) {
    int e = blockIdx.x * 256 + threadIdx.x;
    if (e >= G_ * 64) return;
    int g = e >> 6, r = e & 63;
    int hh = r >> 5, p = (r >> 2) & 7, hp = r & 3;
    int h = hh * 4 + hp;
    float w0 = gvfW[(size_t)g * 128 + h * 16 + 2 * p];
    float w1 = gvfW[(size_t)g * 128 + h * 16 + 2 * p + 1];
    unsigned u0 = (unsigned)__half_as_ushort(__float2half(w0)); u0 |= u0 << 16;
    unsigned u1 = (unsigned)__half_as_ushort(__float2half(w1)); u1 |= u1 << 16;
    uint2 o; o.x = u0; o.y = u1;
    gvfWl[e] = o;   // index = g*64 + hh*32 + p*4 + hp == e
}

// ================= main kernel =================
__global__ __launch_bounds__(THREADS, 1)
void nibbler_fused_kernel(const float* __restrict__ obs,
                          const int*   __restrict__ gidx,
                          float* __restrict__ out) {
    extern __shared__ char smem[];
    uint2*  sObs   = reinterpret_cast<uint2*>(smem + OBS_OFF);
    float*  sQf    = reinterpret_cast<float*>(smem + SQ_OFF);
    float2* sStage = reinterpret_cast<float2*>(smem + STG_OFF);

    const int t     = threadIdx.x;
    const int bBase = blockIdx.x * BM;

    const uint32_t sqA  = (uint32_t)__cvta_generic_to_shared(smem + SQ_OFF);
    const uint32_t wdA  = (uint32_t)__cvta_generic_to_shared(smem + WD_OFF);
    const uint32_t idxA = (uint32_t)__cvta_generic_to_shared(smem + IDX_OFF);

    // ---- issue phase-1 tile 0 immediately ----
    {
        const uint4* src = reinterpret_cast<const uint4*>(qT1g);
        CPA16(sqA + t * 16, src + t);
        CPA16(sqA + (512 + t) * 16, src + 512 + t);
        if (t < 256) CPA16(sqA + (1024 + t) * 16, src + 1024 + t);
        CPCOMMIT();
    }

    // ---- Phase 0: obs -> smem as 4-row quads ----
    for (int e = t; e < 4 * (OBS_ / 4); e += THREADS) {
        int q = e >> 10;
        int f = (e & 1023) * 4;
        float4 v0 = *reinterpret_cast<const float4*>(&obs[(size_t)(bBase + 4 * q + 0) * OBS_ + f]);
        float4 v1 = *reinterpret_cast<const float4*>(&obs[(size_t)(bBase + 4 * q + 1) * OBS_ + f]);
        float4 v2 = *reinterpret_cast<const float4*>(&obs[(size_t)(bBase + 4 * q + 2) * OBS_ + f]);
        float4 v3 = *reinterpret_cast<const float4*>(&obs[(size_t)(bBase + 4 * q + 3) * OBS_ + f]);
        uint2* dst = &sObs[q * QSTRIDE + f];
        __half2 a0 = __floats2half2_rn(v0.x, v1.x), b0 = __floats2half2_rn(v2.x, v3.x);
        __half2 a1 = __floats2half2_rn(v0.y, v1.y), b1 = __floats2half2_rn(v2.y, v3.y);
        __half2 a2 = __floats2half2_rn(v0.z, v1.z), b2 = __floats2half2_rn(v2.z, v3.z);
        __half2 a3 = __floats2half2_rn(v0.w, v1.w), b3 = __floats2half2_rn(v2.w, v3.w);
        uint4 s0, s1;
        s0.x = *reinterpret_cast<unsigned*>(&a0); s0.y = *reinterpret_cast<unsigned*>(&b0);
        s0.z = *reinterpret_cast<unsigned*>(&a1); s0.w = *reinterpret_cast<unsigned*>(&b1);
        s1.x = *reinterpret_cast<unsigned*>(&a2); s1.y = *reinterpret_cast<unsigned*>(&b2);
        s1.z = *reinterpret_cast<unsigned*>(&a3); s1.w = *reinterpret_cast<unsigned*>(&b3);
        *reinterpret_cast<uint4*>(dst)     = s0;
        *reinterpret_cast<uint4*>(dst + 2) = s1;
    }

    const int sp = t & 3;             // quad: batch rows 4sp..4sp+3
    const int gs = (t >> 2) & 63;     // gvf slot
    const int hh = t >> 8;            // head half: h in [4hh, 4hh+4)
    const uint2* qrow = sObs + sp * QSTRIDE;

    u64 acc[4][9];
#pragma unroll
    for (int r = 0; r < 4; r++)
#pragma unroll
        for (int ap = 0; ap < 9; ap++) acc[r][ap] = 0ULL;

    // ======= Phase 1: obs part of q (double-buffered cp.async) =======
    const int slot = t >> 2;          // 0..127 feature slot
    for (int ti = 0; ti < NT1; ti++) {
        CPWAIT0();
        __syncthreads();
        if (ti + 1 < NT1) {
            const uint4* src = reinterpret_cast<const uint4*>(qT1g) + (ti + 1) * 1280;
            uint32_t dst = sqA + ((ti + 1) & 1) * 20480;
            CPA16(dst + t * 16, src + t);
            CPA16(dst + (512 + t) * 16, src + 512 + t);
            if (t < 256) CPA16(dst + (1024 + t) * 16, src + 1024 + t);
            CPCOMMIT();
        }
        if (ti == NT1 - 1) {
            // issue phase-2 tile-0 weights + idx (G2 group)
            const uint4* srcW = reinterpret_cast<const uint4*>(gvfWl);
#pragma unroll
            for (int j = 0; j < 4; j++) {
                int e = j * THREADS + t;
                int gg = e >> 5, k = e & 31;
                CPA16(wdA + gg * 544 + k * 16, srcW + e);
            }
            if (t < 256) {
                int gg = t >> 2, j = t & 3;
                CPA16(idxA + gg * 80 + j * 16, gidx + (size_t)gg * 16 + j * 4);
            }
            CPCOMMIT();
        }
        const float* buf = sQf + (ti & 1) * 5120;
        const int ft = ti * FT;
#pragma unroll
        for (int k = 0; k < 2; k++) {
            int fr = slot + k * 128;
            const float* qr = buf + fr * 20;
            const ulonglong2* q2 = reinterpret_cast<const ulonglong2*>(qr);
            u64 w2[9];
            ulonglong2 qa = q2[0], qb = q2[1], qc = q2[2], qd = q2[3];
            w2[0] = qa.x; w2[1] = qa.y; w2[2] = qb.x; w2[3] = qb.y;
            w2[4] = qc.x; w2[5] = qc.y; w2[6] = qd.x; w2[7] = qd.y;
            w2[8] = *reinterpret_cast<const u64*>(qr + 16);
            uint2 xv = qrow[ft + fr];
            float2 c01 = __half22float2(as_h2(xv.x));
            float2 c23 = __half22float2(as_h2(xv.y));
            u64 fd[4] = { dup2(c01.x), dup2(c01.y), dup2(c23.x), dup2(c23.y) };
#pragma unroll
            for (int r = 0; r < 4; r++)
#pragma unroll
                for (int ap = 0; ap < 9; ap++)
                    acc[r][ap] = ffma2(fd[r], w2[ap], acc[r][ap]);
        }
    }

    // ======= Phase 2: GVF part (single-buffer sQ, split compute) =======
    const __half2 hz = __floats2half2_rn(0.f, 0.f);
    const char* wdRow = smem + WD_OFF + gs * 544 + hh * 256;
    const int*  ip    = reinterpret_cast<const int*>(smem + IDX_OFF) + gs * 20;

    for (int ti = 0; ti < NT2; ti++) {
        __syncthreads();                       // sync1: sQ free (prev (b) done)
        {
            const uint4* src = reinterpret_cast<const uint4*>(qT2g) + (size_t)ti * 2600;
#pragma unroll
            for (int j = 0; j < 5; j++)
                CPA16(sqA + (j * 512 + t) * 16, src + j * 512 + t);
            if (t < 40) CPA16(sqA + (2560 + t) * 16, src + 2560 + t);
            CPCOMMIT();
        }
        CPWAIT1();                             // G2(ti) (weights+idx) done
        __syncthreads();                       // sync2: weights/idx visible

        // ---- (a): gathers + HFMA2 (does not touch sQ) ----
        __half2 f01[4], f23[4];
#pragma unroll
        for (int j = 0; j < 4; j++) { f01[j] = hz; f23[j] = hz; }
#pragma unroll
        for (int c = 0; c < 2; c++) {
            int4 ia = *reinterpret_cast<const int4*>(ip + c * 8);
            int4 ib = *reinterpret_cast<const int4*>(ip + c * 8 + 4);
            int id[8] = { ia.x, ia.y, ia.z, ia.w, ib.x, ib.y, ib.z, ib.w };
#pragma unroll
            for (int pq = 0; pq < 4; pq++) {
                uint2 x0 = qrow[id[2 * pq]];
                uint2 x1 = qrow[id[2 * pq + 1]];
                int p = c * 4 + pq;
                uint4 wA = *reinterpret_cast<const uint4*>(wdRow + p * 32);
                uint4 wB = *reinterpret_cast<const uint4*>(wdRow + p * 32 + 16);
                f01[0] = __hfma2(as_h2(x0.x), as_h2(wA.x), f01[0]);
                f23[0] = __hfma2(as_h2(x0.y), as_h2(wA.x), f23[0]);
                f01[0] = __hfma2(as_h2(x1.x), as_h2(wA.y), f01[0]);
                f23[0] = __hfma2(as_h2(x1.y), as_h2(wA.y), f23[0]);
                f01[1] = __hfma2(as_h2(x0.x), as_h2(wA.z), f01[1]);
                f23[1] = __hfma2(as_h2(x0.y), as_h2(wA.z), f23[1]);
                f01[1] = __hfma2(as_h2(x1.x), as_h2(wA.w), f01[1]);
                f23[1] = __hfma2(as_h2(x1.y), as_h2(wA.w), f23[1]);
                f01[2] = __hfma2(as_h2(x0.x), as_h2(wB.x), f01[2]);
                f23[2] = __hfma2(as_h2(x0.y), as_h2(wB.x), f23[2]);
                f01[2] = __hfma2(as_h2(x1.x), as_h2(wB.y), f01[2]);
                f23[2] = __hfma2(as_h2(x1.y), as_h2(wB.y), f23[2]);
                f01[3] = __hfma2(as_h2(x0.x), as_h2(wB.z), f01[3]);
                f23[3] = __hfma2(as_h2(x0.y), as_h2(wB.z), f23[3]);
                f01[3] = __hfma2(as_h2(x1.x), as_h2(wB.w), f01[3]);
                f23[3] = __hfma2(as_h2(x1.y), as_h2(wB.w), f23[3]);
            }
        }

        CPWAIT0();                             // sQ tile ready
        __syncthreads();                       // sync3: sQ visible; weights free

        if (ti + 1 < NT2) {                    // issue G2(ti+1), hidden by (b)
            const uint4* srcW = reinterpret_cast<const uint4*>(gvfWl) + (size_t)(ti + 1) * 2048;
#pragma unroll
            for (int j = 0; j < 4; j++) {
                int e = j * THREADS + t;
                int gg = e >> 5, k = e & 31;
                CPA16(wdA + gg * 544 + k * 16, srcW + e);
            }
            if (t < 256) {
                int gg = t >> 2, j = t & 3;
                CPA16(idxA + gg * 80 + j * 16,
                      gidx + (size_t)((ti + 1) * GT + gg) * 16 + j * 4);
            }
            CPCOMMIT();
        }

        // ---- (b): q-accumulate over this thread's 4 heads ----
#pragma unroll
        for (int hp = 0; hp < 4; hp++) {
            int h = hh * 4 + hp;
            __half2 g01 = __hmax2(f01[hp], hz);
            __half2 g23 = __hmax2(f23[hp], hz);
            float2 c01 = __half22float2(g01);
            float2 c23 = __half22float2(g23);
            u64 fd[4] = { dup2(c01.x), dup2(c01.y), dup2(c23.x), dup2(c23.y) };
            const float* qr = sQf + (h * HS + gs) * 20;
            const ulonglong2* q2 = reinterpret_cast<const ulonglong2*>(qr);
            u64 w2[9];
            ulonglong2 qa = q2[0], qb = q2[1], qc = q2[2], qd = q2[3];
            w2[0] = qa.x; w2[1] = qa.y; w2[2] = qb.x; w2[3] = qb.y;
            w2[4] = qc.x; w2[5] = qc.y; w2[6] = qd.x; w2[7] = qd.y;
            w2[8] = *reinterpret_cast<const u64*>(qr + 16);
#pragma unroll
            for (int r = 0; r < 4; r++)
#pragma unroll
                for (int ap = 0; ap < 9; ap++)
                    acc[r][ap] = ffma2(fd[r], w2[ap], acc[r][ap]);
        }
    }

    // ======= Phase 3: reduction =======
    __syncthreads();   // all smem reads done; stage aliases weights
    const int lane = t & 31;
    const int wid  = t >> 5;
#pragma unroll
    for (int r = 0; r < 4; r++) {
#pragma unroll
        for (int ap = 0; ap < 9; ap++) {
            float2 v = unpack2(acc[r][ap]);
            v.x += __shfl_xor_sync(0xffffffffu, v.x, 4);
            v.y += __shfl_xor_sync(0xffffffffu, v.y, 4);
            v.x += __shfl_xor_sync(0xffffffffu, v.x, 8);
            v.y += __shfl_xor_sync(0xffffffffu, v.y, 8);
            v.x += __shfl_xor_sync(0xffffffffu, v.x, 16);
            v.y += __shfl_xor_sync(0xffffffffu, v.y, 16);
            if (lane < 4)
                sStage[((wid * 4 + lane) * 4 + r) * 9 + ap] = v;
        }
    }
    __syncthreads();

    if (t < BM * 9) {
        int bl = t / 9, ap = t - bl * 9;   // bl = 4*quad + r
        int quad = bl >> 2, r = bl & 3;
        float sx = 0.f, sy = 0.f;
#pragma unroll
        for (int w = 0; w < 16; w++) {
            float2 v = sStage[((w * 4 + quad) * 4 + r) * 9 + ap];
            sx += v.x; sy += v.y;
        }
        size_t o = (size_t)(bBase + bl) * A_ + 2 * ap;
        out[o]     = sx;
        out[o + 1] = sy;
    }
}

extern "C" void kernel_launch(void* const* d_in, const int* in_sizes, int n_in,
                              void* d_out, int out_size) {
    const float* obs  = (const float*)d_in[0];
    const float* gvfW = (const float*)d_in[1];
    const float* qW   = (const float*)d_in[2];
    const int*   gidx = (const int*)d_in[3];
    float* out = (float*)d_out;

    prep_qT1<<<(NT1 * FT * 20 + 255) / 256, 256>>>(qW);
    prep_qT2<<<(NT2 * 520 * 20 + 255) / 256, 256>>>(qW);
    prep_gvfWl<<<(G_ * 64 + 255) / 256, 256>>>(gvfW);

    cudaFuncSetAttribute(nibbler_fused_kernel,
                         cudaFuncAttributeMaxDynamicSharedMemorySize, SMEM_BYTES);
    nibbler_fused_kernel<<<B_ / BM, THREADS, SMEM_BYTES>>>(obs, gidx, out);
}